// round 1
// baseline (speedup 1.0000x reference)
#include <cuda_runtime.h>

// SpatialCorrelationSampler: out[b, dy*9+dx, h, w] =
//   sum_c in1[b,c,h,w] * in2_zeropad4[b,c,h+dy,w+dx],  dy,dx in [0,9)
//
// Shapes: in1,in2 (B=4, C=256, H=128, W=128) fp32; out (B, 81, H, W) fp32.

namespace {

constexpr int C = 256, H = 128, W = 128;
constexpr int PATCH = 9, PAD = 4;

constexpr int TH = 8;          // tile rows
constexpr int TW = 32;         // tile cols
constexpr int CC = 8;          // channels per smem chunk
constexpr int S2H = TH + 8;    // 16 (halo rows)
constexpr int S2W = TW + 8;    // 40 (halo cols)
constexpr int NTHREADS = 8 * TH * PATCH;        // 8 strips * 8 rows * 9 dy = 576
constexpr int S1_V4 = CC * TH * TW / 4;         // 512 float4
constexpr int S2_V4 = CC * S2H * S2W / 4;       // 1280 float4
constexpr int NCHUNK = C / CC;                  // 32
constexpr int STRIDE_V4 = CC * H * W / 4;       // float4 stride per chunk

__global__ __launch_bounds__(NTHREADS)
void corr_kernel(const float* __restrict__ in1,
                 const float* __restrict__ in2,
                 float* __restrict__ out) {
    __shared__ float4 s1[S1_V4];
    __shared__ float4 s2[S2_V4];

    const int b  = blockIdx.z;
    const int h0 = blockIdx.y * TH;
    const int w0 = blockIdx.x * TW;
    const int tid = threadIdx.x;

    // ------------- fixed load assignments (channel base advances per chunk) ----
    // s1: threads [0,512) each own one float4 of the in1 tile.
    const float4* g1 = nullptr;
    if (tid < S1_V4) {
        int c    = tid >> 6;       // / (TH*TW/4 = 64)
        int rem  = tid & 63;
        int row  = rem >> 3;
        int col4 = rem & 7;
        g1 = (const float4*)(in1 +
            ((((size_t)b * C + c) * H + (h0 + row)) * W + w0 + col4 * 4));
    }
    // s2: up to 3 float4 per thread (halo tile, zero-filled out of range).
    const float4* g2[3];
    bool v2ok[3];
    int  s2idx[3];
#pragma unroll
    for (int i = 0; i < 3; ++i) {
        int f = tid + i * NTHREADS;
        s2idx[i] = f;
        g2[i] = nullptr;
        v2ok[i] = false;
        if (f < S2_V4) {
            int c    = f / (S2H * S2W / 4);   // /160
            int rem  = f % (S2H * S2W / 4);
            int row  = rem / (S2W / 4);       // /10
            int col4 = rem % (S2W / 4);
            int gy = h0 + row - PAD;
            int gx = w0 + col4 * 4 - PAD;     // gx % 4 == 0, so all-in or all-out
            if (gy >= 0 && gy < H && gx >= 0 && gx < W) {
                g2[i] = (const float4*)(in2 +
                    ((((size_t)b * C + c) * H + gy) * W + gx));
                v2ok[i] = true;
            }
        }
    }

    // ------------- compute-role mapping ---------------------------------------
    const int sx = tid & 7;          // 4-pixel strip within row
    const int hy = (tid >> 3) & 7;   // row within tile
    const int dy = tid >> 6;         // 0..8

    float acc[9][4];
#pragma unroll
    for (int i = 0; i < 9; ++i)
#pragma unroll
        for (int j = 0; j < 4; ++j) acc[i][j] = 0.f;

    const float4 zero4 = make_float4(0.f, 0.f, 0.f, 0.f);

    // prefetch chunk 0 into registers
    float4 p1 = (tid < S1_V4) ? __ldg(g1) : zero4;
    float4 p2[3];
#pragma unroll
    for (int i = 0; i < 3; ++i) p2[i] = v2ok[i] ? __ldg(g2[i]) : zero4;

    const float* s1f = (const float*)s1;
    const float* s2f = (const float*)s2;
    const int s1base = hy * TW + sx * 4;
    const int s2base = (hy + dy) * S2W + sx * 4;

    for (int ch = 0; ch < NCHUNK; ++ch) {
        // commit prefetched chunk to smem
        if (tid < S1_V4) s1[tid] = p1;
#pragma unroll
        for (int i = 0; i < 3; ++i)
            if (s2idx[i] < S2_V4) s2[s2idx[i]] = p2[i];

        // issue next chunk's loads (register double-buffer)
        if (ch + 1 < NCHUNK) {
            if (tid < S1_V4) { g1 += STRIDE_V4; p1 = __ldg(g1); }
#pragma unroll
            for (int i = 0; i < 3; ++i)
                if (v2ok[i]) { g2[i] += STRIDE_V4; p2[i] = __ldg(g2[i]); }
        }
        __syncthreads();   // chunk visible

#pragma unroll
        for (int c = 0; c < CC; ++c) {
            float4 a = *(const float4*)&s1f[c * (TH * TW) + s1base];
            float r[12];
#pragma unroll
            for (int j = 0; j < 3; ++j) {
                float4 t = *(const float4*)&s2f[c * (S2H * S2W) + s2base + j * 4];
                r[4 * j + 0] = t.x; r[4 * j + 1] = t.y;
                r[4 * j + 2] = t.z; r[4 * j + 3] = t.w;
            }
#pragma unroll
            for (int dx = 0; dx < 9; ++dx) {
                acc[dx][0] = fmaf(a.x, r[dx + 0], acc[dx][0]);
                acc[dx][1] = fmaf(a.y, r[dx + 1], acc[dx][1]);
                acc[dx][2] = fmaf(a.z, r[dx + 2], acc[dx][2]);
                acc[dx][3] = fmaf(a.w, r[dx + 3], acc[dx][3]);
            }
        }
        __syncthreads();   // compute done before next STS overwrites
    }

    // ------------- epilogue ----------------------------------------------------
    const int h = h0 + hy;
    const int w = w0 + sx * 4;
#pragma unroll
    for (int dx = 0; dx < 9; ++dx) {
        int p = dy * 9 + dx;
        float4 v = make_float4(acc[dx][0], acc[dx][1], acc[dx][2], acc[dx][3]);
        *(float4*)&out[(((size_t)b * (PATCH * PATCH) + p) * H + h) * W + w] = v;
    }
}

}  // namespace

extern "C" void kernel_launch(void* const* d_in, const int* in_sizes, int n_in,
                              void* d_out, int out_size) {
    const float* in1 = (const float*)d_in[0];
    const float* in2 = (const float*)d_in[1];
    float* out = (float*)d_out;

    int B = in_sizes[0] / (C * H * W);   // = 4 for this problem
    dim3 grid(W / TW, H / TH, B);        // (4, 16, B)
    corr_kernel<<<grid, NTHREADS>>>(in1, in2, out);
}

// round 2
// speedup vs baseline: 1.0838x; 1.0838x over previous
#include <cuda_runtime.h>
#include <cstdint>

// SpatialCorrelationSampler: out[b, dy*9+dx, h, w] =
//   sum_c in1[b,c,h,w] * in2_zeropad4[b,c,h+dy,w+dx],  dy,dx in [0,9)
// Shapes: in1,in2 (B=4, C=256, H=128, W=128) fp32; out (B, 81, H, W) fp32.

namespace {

constexpr int C = 256, H = 128, W = 128;
constexpr int PATCH = 9, PAD = 4;

constexpr int TH = 8;           // tile rows
constexpr int TW = 32;          // tile cols
constexpr int CC = 8;           // channels per smem chunk
constexpr int S2H = TH + 8;     // 16
constexpr int S2W = TW + 8;     // 40
constexpr int NTHREADS = 8 * TH * PATCH;    // 576
constexpr int S1_V4 = CC * TH * TW / 4;     // 512 float4 per stage
constexpr int S2_V4 = CC * S2H * S2W / 4;   // 1280 float4 per stage
constexpr int NCHUNK = C / CC;              // 32
constexpr int STRIDE = CC * H * W;          // float stride per chunk

constexpr int STAGES = 3;
constexpr int S1_FLOATS = CC * TH * TW;     // 2048
constexpr int S2_FLOATS = CC * S2H * S2W;   // 5120
constexpr int SMEM_BYTES = STAGES * (S1_FLOATS + S2_FLOATS) * 4;  // 86016

__device__ __forceinline__ void cp16(uint32_t dst_smem, const void* src) {
    asm volatile("cp.async.cg.shared.global [%0], [%1], 16;"
                 :: "r"(dst_smem), "l"(src));
}
__device__ __forceinline__ void cp_commit() {
    asm volatile("cp.async.commit_group;" ::: "memory");
}
__device__ __forceinline__ void cp_wait2() {
    asm volatile("cp.async.wait_group 2;" ::: "memory");
}

__global__ __launch_bounds__(NTHREADS)
void corr_kernel(const float* __restrict__ in1,
                 const float* __restrict__ in2,
                 float* __restrict__ out) {
    extern __shared__ float smem[];
    // layout: s1 stages [0, 3*2048), s2 stages [3*2048, 3*2048 + 3*5120)
    float* s1s = smem;
    float* s2s = smem + STAGES * S1_FLOATS;
    const uint32_t s1s_addr = (uint32_t)__cvta_generic_to_shared(s1s);
    const uint32_t s2s_addr = (uint32_t)__cvta_generic_to_shared(s2s);

    const int b  = blockIdx.z;
    const int h0 = blockIdx.y * TH;
    const int w0 = blockIdx.x * TW;
    const int tid = threadIdx.x;

    // ---------------- fixed copy assignments --------------------------------
    // s1: threads [0,512) each own one float4 of the in1 chunk tile.
    const char* g1 = nullptr;
    if (tid < S1_V4) {
        int c    = tid >> 6;      // / 64
        int rem  = tid & 63;
        int row  = rem >> 3;
        int col4 = rem & 7;
        g1 = (const char*)(in1 +
            ((((size_t)b * C + c) * H + (h0 + row)) * W + w0 + col4 * 4));
    }
    // s2: up to 3 float4 per thread; OOB slots are zeroed once (never copied).
    const char* g2[3];
    bool v2ok[3];
    int  s2idx[3];
#pragma unroll
    for (int i = 0; i < 3; ++i) {
        int f = tid + i * NTHREADS;
        s2idx[i] = f;
        g2[i] = nullptr;
        v2ok[i] = false;
        if (f < S2_V4) {
            int c    = f / (S2H * S2W / 4);   // /160
            int rem  = f % (S2H * S2W / 4);
            int row  = rem / (S2W / 4);       // /10
            int col4 = rem % (S2W / 4);
            int gy = h0 + row - PAD;
            int gx = w0 + col4 * 4 - PAD;     // 16B aligned: all-in or all-out
            if (gy >= 0 && gy < H && gx >= 0 && gx < W) {
                g2[i] = (const char*)(in2 +
                    ((((size_t)b * C + c) * H + gy) * W + gx));
                v2ok[i] = true;
            } else {
                // zero this OOB slot in all stages (disjoint from cp targets)
                float4 z = make_float4(0.f, 0.f, 0.f, 0.f);
#pragma unroll
                for (int s = 0; s < STAGES; ++s)
                    *(float4*)&s2s[s * S2_FLOATS + f * 4] = z;
            }
        }
    }

    // ---------------- async-copy issue helper (manual ring) ------------------
    // chunk ch -> stage ch % 3. Pointers advance by STRIDE floats per chunk.
    const char* g1c = g1;
    const char* g2c[3] = {g2[0], g2[1], g2[2]};

    auto issue_chunk = [&](int ch) {
        int s = ch % STAGES;
        if (tid < S1_V4) {
            cp16(s1s_addr + (s * S1_FLOATS + tid * 4) * 4, g1c);
            g1c += STRIDE * 4;
        }
#pragma unroll
        for (int i = 0; i < 3; ++i) {
            if (v2ok[i]) {
                cp16(s2s_addr + (s * S2_FLOATS + s2idx[i] * 4) * 4, g2c[i]);
                g2c[i] += STRIDE * 4;
            }
        }
        cp_commit();
    };

    // prologue: stages 0 and 1 in flight
    issue_chunk(0);
    issue_chunk(1);

    // ---------------- compute-role mapping ----------------------------------
    const int sx = tid & 7;          // 4-pixel strip within row
    const int hy = (tid >> 3) & 7;   // row within tile
    const int dy = tid >> 6;         // 0..8

    float acc[9][4];
#pragma unroll
    for (int i = 0; i < 9; ++i)
#pragma unroll
        for (int j = 0; j < 4; ++j) acc[i][j] = 0.f;

    const int s1base = hy * TW + sx * 4;
    const int s2base = (hy + dy) * S2W + sx * 4;

    for (int ch = 0; ch < NCHUNK; ++ch) {
        // keep pipeline 2 deep
        if (ch + 2 < NCHUNK) issue_chunk(ch + 2);
        else cp_commit();                 // keep group accounting uniform

        cp_wait2();                        // chunk ch's group complete
        __syncthreads();                   // visible to all threads

        const float* s1f = s1s + (ch % STAGES) * S1_FLOATS;
        const float* s2f = s2s + (ch % STAGES) * S2_FLOATS;

#pragma unroll
        for (int c = 0; c < CC; ++c) {
            float4 a = *(const float4*)&s1f[c * (TH * TW) + s1base];
            float r[12];
#pragma unroll
            for (int j = 0; j < 3; ++j) {
                float4 t = *(const float4*)&s2f[c * (S2H * S2W) + s2base + j * 4];
                r[4 * j + 0] = t.x; r[4 * j + 1] = t.y;
                r[4 * j + 2] = t.z; r[4 * j + 3] = t.w;
            }
#pragma unroll
            for (int dx = 0; dx < 9; ++dx) {
                acc[dx][0] = fmaf(a.x, r[dx + 0], acc[dx][0]);
                acc[dx][1] = fmaf(a.y, r[dx + 1], acc[dx][1]);
                acc[dx][2] = fmaf(a.z, r[dx + 2], acc[dx][2]);
                acc[dx][3] = fmaf(a.w, r[dx + 3], acc[dx][3]);
            }
        }
        __syncthreads();   // all reads done before stage gets overwritten
    }

    // ---------------- epilogue ------------------------------------------------
    const int h = h0 + hy;
    const int w = w0 + sx * 4;
#pragma unroll
    for (int dx = 0; dx < 9; ++dx) {
        int p = dy * 9 + dx;
        float4 v = make_float4(acc[dx][0], acc[dx][1], acc[dx][2], acc[dx][3]);
        *(float4*)&out[(((size_t)b * (PATCH * PATCH) + p) * H + h) * W + w] = v;
    }
}

}  // namespace

extern "C" void kernel_launch(void* const* d_in, const int* in_sizes, int n_in,
                              void* d_out, int out_size) {
    const float* in1 = (const float*)d_in[0];
    const float* in2 = (const float*)d_in[1];
    float* out = (float*)d_out;

    cudaFuncSetAttribute(corr_kernel,
                         cudaFuncAttributeMaxDynamicSharedMemorySize,
                         SMEM_BYTES);

    int B = in_sizes[0] / (C * H * W);   // = 4
    dim3 grid(W / TW, H / TH, B);        // (4, 16, B) = 256 blocks
    corr_kernel<<<grid, NTHREADS, SMEM_BYTES>>>(in1, in2, out);
}